// round 3
// baseline (speedup 1.0000x reference)
#include <cuda_runtime.h>

// ScaledDotProductAttention: B=32, Q=1024, K=1024, D=64, fp32.
// out = [context (32*1024*64) | attn (32*1024*1024)] concatenated.
// mask: delivered as 4-byte elements (int32 0/1 or float32 0.0/1.0);
//       nonzero => score = -1e9.

#define BQ 32        // q rows per block
#define KC 256       // k-chunk width (gemm1 cols / gemm2 reduction rows)
#define SPITCH 1032  // score row pitch (floats)
#define NTHREADS 512

// smem layout (floats):
//   sQ : 64 x 32  (d-major: sQ[d*32+r])              2048
//   sKV: gemm1 K chunk [d*KC + j] / gemm2 V [kk*64+d] 16384
//   sS : 32 x SPITCH                                  33024
#define SQ_OFF  0
#define SKV_OFF 2048
#define SS_OFF  (2048 + 16384)
#define SMEM_FLOATS (2048 + 16384 + 32 * SPITCH)

__global__ __launch_bounds__(NTHREADS, 1)
void sdpa_kernel(const float* __restrict__ Qg, const float* __restrict__ Kg,
                 const float* __restrict__ Vg, const unsigned int* __restrict__ Mg,
                 float* __restrict__ ctx, float* __restrict__ attn)
{
    extern __shared__ float smem[];
    float* sQ  = smem + SQ_OFF;
    float* sKV = smem + SKV_OFF;
    float* sS  = smem + SS_OFF;

    const int tid = threadIdx.x;
    const int b  = blockIdx.y;
    const int q0 = blockIdx.x * BQ;

    const float* Qb = Qg + ((size_t)b * 1024 + q0) * 64;
    const float* Kb = Kg + (size_t)b * 1024 * 64;
    const float* Vb = Vg + (size_t)b * 1024 * 64;
    const unsigned int* Mb = Mg + ((size_t)b * 1024 + q0) * 1024;
    float* attnb = attn + ((size_t)b * 1024 + q0) * 1024;
    float* ctxb  = ctx  + ((size_t)b * 1024 + q0) * 64;

    // ---- load Q tile (32 x 64), stored d-major for broadcast reads ----
    for (int idx = tid; idx < 32 * 16; idx += NTHREADS) {
        int r = idx >> 4, dg = idx & 15;
        float4 v = *(const float4*)(Qb + r * 64 + dg * 4);
        sQ[(dg * 4 + 0) * 32 + r] = v.x;
        sQ[(dg * 4 + 1) * 32 + r] = v.y;
        sQ[(dg * 4 + 2) * 32 + r] = v.z;
        sQ[(dg * 4 + 3) * 32 + r] = v.w;
    }

    // ===================== GEMM1: S = QK^T / 8, masked =====================
    {
        const int tc  = tid & 63;   // col group -> cols tc*4 .. tc*4+3 (within chunk)
        const int trw = tid >> 6;   // row group -> rows trw*4 .. trw*4+3
        for (int kc = 0; kc < 1024; kc += KC) {
            __syncthreads();
            // load K chunk [KC x 64] -> sKV[d*KC + j]
            for (int idx = tid; idx < KC * 16; idx += NTHREADS) {
                int j = idx >> 4, dg = idx & 15;
                float4 v = *(const float4*)(Kb + (size_t)(kc + j) * 64 + dg * 4);
                sKV[(dg * 4 + 0) * KC + j] = v.x;
                sKV[(dg * 4 + 1) * KC + j] = v.y;
                sKV[(dg * 4 + 2) * KC + j] = v.z;
                sKV[(dg * 4 + 3) * KC + j] = v.w;
            }
            __syncthreads();

            float acc[4][4];
            #pragma unroll
            for (int i = 0; i < 4; i++)
                #pragma unroll
                for (int j = 0; j < 4; j++) acc[i][j] = 0.0f;

            #pragma unroll 16
            for (int d = 0; d < 64; d++) {
                float4 qv = *(const float4*)(sQ + d * 32 + trw * 4);   // broadcast in warp
                float4 kv = *(const float4*)(sKV + d * KC + tc * 4);
                float q4[4] = {qv.x, qv.y, qv.z, qv.w};
                float k4[4] = {kv.x, kv.y, kv.z, kv.w};
                #pragma unroll
                for (int i = 0; i < 4; i++)
                    #pragma unroll
                    for (int j = 0; j < 4; j++)
                        acc[i][j] += q4[i] * k4[j];
            }

            #pragma unroll
            for (int i = 0; i < 4; i++) {
                int r = trw * 4 + i;
                // mask elements are 4-byte (int32 0/1 or float32 0.0/1.0): nonzero == masked
                uint4 m = *(const uint4*)(Mb + (size_t)r * 1024 + kc + tc * 4);
                float4 o;
                o.x = m.x ? -1e9f : acc[i][0] * 0.125f;
                o.y = m.y ? -1e9f : acc[i][1] * 0.125f;
                o.z = m.z ? -1e9f : acc[i][2] * 0.125f;
                o.w = m.w ? -1e9f : acc[i][3] * 0.125f;
                *(float4*)(sS + r * SPITCH + kc + tc * 4) = o;
            }
        }
    }
    __syncthreads();

    // ===================== softmax (per row) + write attn =====================
    {
        const int lane = tid & 31;
        const int w    = tid >> 5;      // 16 warps, 2 rows each
        #pragma unroll
        for (int rr = 0; rr < 2; rr++) {
            int r = w * 2 + rr;
            float* row = sS + r * SPITCH;

            float mx = -3.4e38f;
            for (int j = lane * 4; j < 1024; j += 128) {
                float4 s = *(const float4*)(row + j);
                mx = fmaxf(mx, fmaxf(fmaxf(s.x, s.y), fmaxf(s.z, s.w)));
            }
            #pragma unroll
            for (int o = 16; o; o >>= 1) mx = fmaxf(mx, __shfl_xor_sync(0xFFFFFFFFu, mx, o));

            float sum = 0.0f;
            for (int j = lane * 4; j < 1024; j += 128) {
                float4 s = *(const float4*)(row + j);
                s.x = __expf(s.x - mx);
                s.y = __expf(s.y - mx);
                s.z = __expf(s.z - mx);
                s.w = __expf(s.w - mx);
                *(float4*)(row + j) = s;
                sum += (s.x + s.y) + (s.z + s.w);
            }
            #pragma unroll
            for (int o = 16; o; o >>= 1) sum += __shfl_xor_sync(0xFFFFFFFFu, sum, o);
            float inv = 1.0f / sum;

            for (int j = lane * 4; j < 1024; j += 128) {
                float4 s = *(const float4*)(row + j);
                s.x *= inv; s.y *= inv; s.z *= inv; s.w *= inv;
                *(float4*)(row + j) = s;
                *(float4*)(attnb + (size_t)r * 1024 + j) = s;   // coalesced
            }
        }
    }

    // ===================== GEMM2: context = P @ V (split-K x2) =====================
    {
        const int group = tid >> 8;       // 0 or 1 (k-split)
        const int t  = tid & 255;
        const int rw = t >> 5;            // rows rw*4 .. rw*4+3
        const int dc = t & 31;            // cols dc*2, dc*2+1

        float acc[4][2];
        #pragma unroll
        for (int i = 0; i < 4; i++) { acc[i][0] = 0.0f; acc[i][1] = 0.0f; }

        for (int kc = 0; kc < 1024; kc += KC) {
            __syncthreads();
            // load V chunk [KC x 64] -> sKV[kk*64 + d]
            for (int idx = tid; idx < KC * 16; idx += NTHREADS) {
                int kk = idx >> 4, dg = idx & 15;
                float4 v = *(const float4*)(Vb + (size_t)(kc + kk) * 64 + dg * 4);
                *(float4*)(sKV + kk * 64 + dg * 4) = v;
            }
            __syncthreads();

            const int kbase = group * (KC / 2);
            for (int kk4 = 0; kk4 < KC / 2; kk4 += 4) {
                float4 p4[4];
                #pragma unroll
                for (int i = 0; i < 4; i++)
                    p4[i] = *(const float4*)(sS + (rw * 4 + i) * SPITCH + kc + kbase + kk4); // broadcast
                #pragma unroll
                for (int u = 0; u < 4; u++) {
                    float2 vv = *(const float2*)(sKV + (kbase + kk4 + u) * 64 + dc * 2);
                    float p0 = (u == 0) ? p4[0].x : (u == 1) ? p4[0].y : (u == 2) ? p4[0].z : p4[0].w;
                    float p1 = (u == 0) ? p4[1].x : (u == 1) ? p4[1].y : (u == 2) ? p4[1].z : p4[1].w;
                    float p2 = (u == 0) ? p4[2].x : (u == 1) ? p4[2].y : (u == 2) ? p4[2].z : p4[2].w;
                    float p3 = (u == 0) ? p4[3].x : (u == 1) ? p4[3].y : (u == 2) ? p4[3].z : p4[3].w;
                    acc[0][0] += p0 * vv.x; acc[0][1] += p0 * vv.y;
                    acc[1][0] += p1 * vv.x; acc[1][1] += p1 * vv.y;
                    acc[2][0] += p2 * vv.x; acc[2][1] += p2 * vv.y;
                    acc[3][0] += p3 * vv.x; acc[3][1] += p3 * vv.y;
                }
            }
        }

        // reduce the two k-split groups through sQ region (2048 floats = 32x64)
        __syncthreads();
        if (group == 1) {
            #pragma unroll
            for (int i = 0; i < 4; i++) {
                sQ[(rw * 4 + i) * 64 + dc * 2 + 0] = acc[i][0];
                sQ[(rw * 4 + i) * 64 + dc * 2 + 1] = acc[i][1];
            }
        }
        __syncthreads();
        if (group == 0) {
            #pragma unroll
            for (int i = 0; i < 4; i++) {
                float2 o;
                o.x = acc[i][0] + sQ[(rw * 4 + i) * 64 + dc * 2 + 0];
                o.y = acc[i][1] + sQ[(rw * 4 + i) * 64 + dc * 2 + 1];
                *(float2*)(ctxb + (size_t)(rw * 4 + i) * 64 + dc * 2) = o;
            }
        }
    }
}

extern "C" void kernel_launch(void* const* d_in, const int* in_sizes, int n_in,
                              void* d_out, int out_size) {
    const float* q = (const float*)d_in[0];
    const float* k = (const float*)d_in[1];
    const float* v = (const float*)d_in[2];
    const unsigned int* m = (const unsigned int*)d_in[3];

    float* ctx  = (float*)d_out;                       // 32*1024*64
    float* attn = (float*)d_out + 32 * 1024 * 64;      // 32*1024*1024

    const size_t smem_bytes = (size_t)SMEM_FLOATS * sizeof(float);  // 205,824 B
    cudaFuncSetAttribute(sdpa_kernel, cudaFuncAttributeMaxDynamicSharedMemorySize,
                         (int)smem_bytes);

    dim3 grid(1024 / BQ, 32);   // (q tiles, batch)
    sdpa_kernel<<<grid, NTHREADS, smem_bytes>>>(q, k, v, m, ctx, attn);
}

// round 5
// speedup vs baseline: 1.0001x; 1.0001x over previous
#include <cuda_runtime.h>

// ScaledDotProductAttention: B=32, Q=1024, K=1024, D=64, fp32.
// out = [context (32*1024*64) | attn (32*1024*1024)] concatenated.
// mask: delivered as 4-byte elements (int32 0/1 or float32 0.0/1.0);
//       nonzero => score = -1e9.

#define BQ 32        // q rows per block
#define KC 256       // k-chunk width (gemm1 cols / gemm2 reduction rows)
#define SPITCH 1032  // score row pitch (floats)
#define NTHREADS 512

// smem layout (floats):
//   sQ : 64 x 32  (d-major: sQ[d*32+r])              2048
//   sKV: gemm1 K chunk [d*KC + j] / gemm2 V [kk*64+d] 16384
//   sS : 32 x SPITCH                                  33024
#define SQ_OFF  0
#define SKV_OFF 2048
#define SS_OFF  (2048 + 16384)
#define SMEM_FLOATS (2048 + 16384 + 32 * SPITCH)

__global__ __launch_bounds__(NTHREADS, 1)
void sdpa_kernel(const float* __restrict__ Qg, const float* __restrict__ Kg,
                 const float* __restrict__ Vg, const unsigned int* __restrict__ Mg,
                 float* __restrict__ ctx, float* __restrict__ attn)
{
    extern __shared__ float smem[];
    float* sQ  = smem + SQ_OFF;
    float* sKV = smem + SKV_OFF;
    float* sS  = smem + SS_OFF;

    const int tid = threadIdx.x;
    const int b  = blockIdx.y;
    const int q0 = blockIdx.x * BQ;

    const float* Qb = Qg + ((size_t)b * 1024 + q0) * 64;
    const float* Kb = Kg + (size_t)b * 1024 * 64;
    const float* Vb = Vg + (size_t)b * 1024 * 64;
    const unsigned int* Mb = Mg + ((size_t)b * 1024 + q0) * 1024;
    float* attnb = attn + ((size_t)b * 1024 + q0) * 1024;
    float* ctxb  = ctx  + ((size_t)b * 1024 + q0) * 64;

    // ---- load Q tile (32 x 64), stored d-major for broadcast reads ----
    for (int idx = tid; idx < 32 * 16; idx += NTHREADS) {
        int r = idx >> 4, dg = idx & 15;
        float4 v = *(const float4*)(Qb + r * 64 + dg * 4);
        sQ[(dg * 4 + 0) * 32 + r] = v.x;
        sQ[(dg * 4 + 1) * 32 + r] = v.y;
        sQ[(dg * 4 + 2) * 32 + r] = v.z;
        sQ[(dg * 4 + 3) * 32 + r] = v.w;
    }

    // ===================== GEMM1: S = QK^T / 8, masked =====================
    {
        const int tc  = tid & 63;   // col group -> cols tc*4 .. tc*4+3 (within chunk)
        const int trw = tid >> 6;   // row group -> rows trw*4 .. trw*4+3
        for (int kc = 0; kc < 1024; kc += KC) {
            __syncthreads();
            // load K chunk [KC x 64] -> sKV[d*KC + j]
            for (int idx = tid; idx < KC * 16; idx += NTHREADS) {
                int j = idx >> 4, dg = idx & 15;
                float4 v = *(const float4*)(Kb + (size_t)(kc + j) * 64 + dg * 4);
                sKV[(dg * 4 + 0) * KC + j] = v.x;
                sKV[(dg * 4 + 1) * KC + j] = v.y;
                sKV[(dg * 4 + 2) * KC + j] = v.z;
                sKV[(dg * 4 + 3) * KC + j] = v.w;
            }
            __syncthreads();

            float acc[4][4];
            #pragma unroll
            for (int i = 0; i < 4; i++)
                #pragma unroll
                for (int j = 0; j < 4; j++) acc[i][j] = 0.0f;

            #pragma unroll 16
            for (int d = 0; d < 64; d++) {
                float4 qv = *(const float4*)(sQ + d * 32 + trw * 4);   // broadcast in warp
                float4 kv = *(const float4*)(sKV + d * KC + tc * 4);
                float q4[4] = {qv.x, qv.y, qv.z, qv.w};
                float k4[4] = {kv.x, kv.y, kv.z, kv.w};
                #pragma unroll
                for (int i = 0; i < 4; i++)
                    #pragma unroll
                    for (int j = 0; j < 4; j++)
                        acc[i][j] += q4[i] * k4[j];
            }

            #pragma unroll
            for (int i = 0; i < 4; i++) {
                int r = trw * 4 + i;
                // mask elements are 4-byte (int32 0/1 or float32 0.0/1.0): nonzero == masked
                uint4 m = *(const uint4*)(Mb + (size_t)r * 1024 + kc + tc * 4);
                float4 o;
                o.x = m.x ? -1e9f : acc[i][0] * 0.125f;
                o.y = m.y ? -1e9f : acc[i][1] * 0.125f;
                o.z = m.z ? -1e9f : acc[i][2] * 0.125f;
                o.w = m.w ? -1e9f : acc[i][3] * 0.125f;
                *(float4*)(sS + r * SPITCH + kc + tc * 4) = o;
            }
        }
    }
    __syncthreads();

    // ===================== softmax (per row) + write attn =====================
    {
        const int lane = tid & 31;
        const int w    = tid >> 5;      // 16 warps, 2 rows each
        #pragma unroll
        for (int rr = 0; rr < 2; rr++) {
            int r = w * 2 + rr;
            float* row = sS + r * SPITCH;

            float mx = -3.4e38f;
            for (int j = lane * 4; j < 1024; j += 128) {
                float4 s = *(const float4*)(row + j);
                mx = fmaxf(mx, fmaxf(fmaxf(s.x, s.y), fmaxf(s.z, s.w)));
            }
            #pragma unroll
            for (int o = 16; o; o >>= 1) mx = fmaxf(mx, __shfl_xor_sync(0xFFFFFFFFu, mx, o));

            float sum = 0.0f;
            for (int j = lane * 4; j < 1024; j += 128) {
                float4 s = *(const float4*)(row + j);
                s.x = __expf(s.x - mx);
                s.y = __expf(s.y - mx);
                s.z = __expf(s.z - mx);
                s.w = __expf(s.w - mx);
                *(float4*)(row + j) = s;
                sum += (s.x + s.y) + (s.z + s.w);
            }
            #pragma unroll
            for (int o = 16; o; o >>= 1) sum += __shfl_xor_sync(0xFFFFFFFFu, sum, o);
            float inv = 1.0f / sum;

            for (int j = lane * 4; j < 1024; j += 128) {
                float4 s = *(const float4*)(row + j);
                s.x *= inv; s.y *= inv; s.z *= inv; s.w *= inv;
                *(float4*)(row + j) = s;
                *(float4*)(attnb + (size_t)r * 1024 + j) = s;   // coalesced
            }
        }
    }

    // ===================== GEMM2: context = P @ V (split-K x2) =====================
    {
        const int group = tid >> 8;       // 0 or 1 (k-split)
        const int t  = tid & 255;
        const int rw = t >> 5;            // rows rw*4 .. rw*4+3
        const int dc = t & 31;            // cols dc*2, dc*2+1

        float acc[4][2];
        #pragma unroll
        for (int i = 0; i < 4; i++) { acc[i][0] = 0.0f; acc[i][1] = 0.0f; }

        for (int kc = 0; kc < 1024; kc += KC) {
            __syncthreads();
            // load V chunk [KC x 64] -> sKV[kk*64 + d]
            for (int idx = tid; idx < KC * 16; idx += NTHREADS) {
                int kk = idx >> 4, dg = idx & 15;
                float4 v = *(const float4*)(Vb + (size_t)(kc + kk) * 64 + dg * 4);
                *(float4*)(sKV + kk * 64 + dg * 4) = v;
            }
            __syncthreads();

            const int kbase = group * (KC / 2);
            for (int kk4 = 0; kk4 < KC / 2; kk4 += 4) {
                float4 p4[4];
                #pragma unroll
                for (int i = 0; i < 4; i++)
                    p4[i] = *(const float4*)(sS + (rw * 4 + i) * SPITCH + kc + kbase + kk4); // broadcast
                #pragma unroll
                for (int u = 0; u < 4; u++) {
                    float2 vv = *(const float2*)(sKV + (kbase + kk4 + u) * 64 + dc * 2);
                    float p0 = (u == 0) ? p4[0].x : (u == 1) ? p4[0].y : (u == 2) ? p4[0].z : p4[0].w;
                    float p1 = (u == 0) ? p4[1].x : (u == 1) ? p4[1].y : (u == 2) ? p4[1].z : p4[1].w;
                    float p2 = (u == 0) ? p4[2].x : (u == 1) ? p4[2].y : (u == 2) ? p4[2].z : p4[2].w;
                    float p3 = (u == 0) ? p4[3].x : (u == 1) ? p4[3].y : (u == 2) ? p4[3].z : p4[3].w;
                    acc[0][0] += p0 * vv.x; acc[0][1] += p0 * vv.y;
                    acc[1][0] += p1 * vv.x; acc[1][1] += p1 * vv.y;
                    acc[2][0] += p2 * vv.x; acc[2][1] += p2 * vv.y;
                    acc[3][0] += p3 * vv.x; acc[3][1] += p3 * vv.y;
                }
            }
        }

        // reduce the two k-split groups through sQ region (2048 floats = 32x64)
        __syncthreads();
        if (group == 1) {
            #pragma unroll
            for (int i = 0; i < 4; i++) {
                sQ[(rw * 4 + i) * 64 + dc * 2 + 0] = acc[i][0];
                sQ[(rw * 4 + i) * 64 + dc * 2 + 1] = acc[i][1];
            }
        }
        __syncthreads();
        if (group == 0) {
            #pragma unroll
            for (int i = 0; i < 4; i++) {
                float2 o;
                o.x = acc[i][0] + sQ[(rw * 4 + i) * 64 + dc * 2 + 0];
                o.y = acc[i][1] + sQ[(rw * 4 + i) * 64 + dc * 2 + 1];
                *(float2*)(ctxb + (size_t)(rw * 4 + i) * 64 + dc * 2) = o;
            }
        }
    }
}

extern "C" void kernel_launch(void* const* d_in, const int* in_sizes, int n_in,
                              void* d_out, int out_size) {
    const float* q = (const float*)d_in[0];
    const float* k = (const float*)d_in[1];
    const float* v = (const float*)d_in[2];
    const unsigned int* m = (const unsigned int*)d_in[3];

    float* ctx  = (float*)d_out;                       // 32*1024*64
    float* attn = (float*)d_out + 32 * 1024 * 64;      // 32*1024*1024

    const size_t smem_bytes = (size_t)SMEM_FLOATS * sizeof(float);  // 205,824 B
    cudaFuncSetAttribute(sdpa_kernel, cudaFuncAttributeMaxDynamicSharedMemorySize,
                         (int)smem_bytes);

    dim3 grid(1024 / BQ, 32);   // (q tiles, batch)
    sdpa_kernel<<<grid, NTHREADS, smem_bytes>>>(q, k, v, m, ctx, attn);
}

// round 7
// speedup vs baseline: 1.4147x; 1.4146x over previous
#include <cuda_runtime.h>
#include <cuda_bf16.h>
#include <cstdint>

// SDPA via warp-level mma.sync (bf16 hi/lo split, 3 products = fp32-grade).
// B=32, Q=K=1024, D=64 fp32. out = [context | attn]. mask 4B, nonzero => p=0.
// CTA: 64 q-rows, 512 thr = 16 warps = (mh 0..3 m16-rowgroup) x (kw 0..3 k-quadrant).
// Warp kw streams chunks c = ph*4+kw (64 K-cols each) over 4 phases.

#define PITCHB 144            // smem row pitch (72 bf16) -> conflict-free ldmatrix
#define CHUNKB (64 * PITCHB)  // 9216 B per 64-row tile

#define SM_QH   0
#define SM_QL   (SM_QH + CHUNKB)
#define SM_KH   (SM_QL + CHUNKB)        // 4 slots
#define SM_KL   (SM_KH + 4 * CHUNKB)
#define SM_VH   (SM_KL + 4 * CHUNKB)
#define SM_VL   (SM_VH + 4 * CHUNKB)
#define SM_Z    (SM_VL + 4 * CHUNKB)    // 64 f32
#define SM_INVZ (SM_Z + 256)            // 64 f32
#define SM_CTX  (SM_INVZ + 256)         // 64x64 f32
#define SM_TOTAL (SM_CTX + 16384)       // 182784 B

__device__ __forceinline__ uint32_t smem_u32(const void* p) {
    uint32_t a;
    asm("{ .reg .u64 t; cvta.to.shared.u64 t, %1; cvt.u32.u64 %0, t; }" : "=r"(a) : "l"(p));
    return a;
}
__device__ __forceinline__ uint32_t b2u(__nv_bfloat162 h) { return *(uint32_t*)&h; }

__device__ __forceinline__ void ldsm_x4(uint32_t a, uint32_t r[4]) {
    asm volatile("ldmatrix.sync.aligned.m8n8.x4.shared.b16 {%0,%1,%2,%3}, [%4];"
                 : "=r"(r[0]), "=r"(r[1]), "=r"(r[2]), "=r"(r[3]) : "r"(a));
}
__device__ __forceinline__ void ldsm_x2(uint32_t a, uint32_t r[2]) {
    asm volatile("ldmatrix.sync.aligned.m8n8.x2.shared.b16 {%0,%1}, [%2];"
                 : "=r"(r[0]), "=r"(r[1]) : "r"(a));
}
__device__ __forceinline__ void ldsm_x2t(uint32_t a, uint32_t r[2]) {
    asm volatile("ldmatrix.sync.aligned.m8n8.x2.trans.shared.b16 {%0,%1}, [%2];"
                 : "=r"(r[0]), "=r"(r[1]) : "r"(a));
}
__device__ __forceinline__ void mma_bf16(float c[4], const uint32_t a[4], const uint32_t b[2]) {
    asm volatile("mma.sync.aligned.m16n8k16.row.col.f32.bf16.bf16.f32 "
                 "{%0,%1,%2,%3}, {%4,%5,%6,%7}, {%8,%9}, {%0,%1,%2,%3};"
                 : "+f"(c[0]), "+f"(c[1]), "+f"(c[2]), "+f"(c[3])
                 : "r"(a[0]), "r"(a[1]), "r"(a[2]), "r"(a[3]), "r"(b[0]), "r"(b[1]));
}

// split fp32 float4 into bf16 hi/lo and store 8B each into pitched smem row
__device__ __forceinline__ void split_store(char* sm, int hoff, int loff,
                                            int row, int dg, float4 v) {
    __nv_bfloat162 h01 = __floats2bfloat162_rn(v.x, v.y);
    __nv_bfloat162 h23 = __floats2bfloat162_rn(v.z, v.w);
    __nv_bfloat162 l01 = __floats2bfloat162_rn(v.x - __low2float(h01), v.y - __high2float(h01));
    __nv_bfloat162 l23 = __floats2bfloat162_rn(v.z - __low2float(h23), v.w - __high2float(h23));
    int off = row * PITCHB + dg * 8;
    *(uint2*)(sm + hoff + off) = make_uint2(b2u(h01), b2u(h23));
    *(uint2*)(sm + loff + off) = make_uint2(b2u(l01), b2u(l23));
}

__global__ __launch_bounds__(512, 1)
void sdpa_mma_kernel(const float* __restrict__ Qg, const float* __restrict__ Kg,
                     const float* __restrict__ Vg, const uint32_t* __restrict__ Mg,
                     float* __restrict__ ctx, float* __restrict__ attn)
{
    extern __shared__ char sm[];
    const uint32_t sb = smem_u32(sm);

    const int tid  = threadIdx.x;
    const int wid  = tid >> 5;
    const int lane = tid & 31;
    const int g    = lane >> 2;       // fragment row group 0..7
    const int t    = lane & 3;        // fragment quad lane
    const int mh   = wid & 3;         // m16 row group
    const int kw   = wid >> 2;        // k quadrant

    const int b  = blockIdx.y;
    const int q0 = blockIdx.x * 64;

    const float* Qb = Qg + ((size_t)b * 1024 + q0) * 64;
    const float* Kb = Kg + (size_t)b * 1024 * 64;
    const float* Vb = Vg + (size_t)b * 1024 * 64;
    const uint32_t* Mb = Mg + ((size_t)b * 1024 + q0) * 1024;
    float* attnb = attn + ((size_t)b * 1024 + q0) * 1024;
    float* ctxb  = ctx  + ((size_t)b * 1024 + q0) * 64;

    const int r0 = mh * 16 + g;       // this lane's fragment rows
    const int r1 = r0 + 8;

    // zero Z accumulators
    if (tid < 64) ((float*)(sm + SM_Z))[tid] = 0.0f;

    // load Q (64x64), fold 1/8 scale, split hi/lo
    #pragma unroll
    for (int it = 0; it < 2; it++) {
        int u = tid + it * 512;           // 1024 float4 units
        int r = u >> 4, dg = u & 15;
        float4 v = *(const float4*)(Qb + (size_t)r * 64 + dg * 4);
        v.x *= 0.125f; v.y *= 0.125f; v.z *= 0.125f; v.w *= 0.125f;
        split_store(sm, SM_QH, SM_QL, r, dg, v);
    }

    float ctxa[8][4];
    #pragma unroll
    for (int j = 0; j < 8; j++)
        #pragma unroll
        for (int i = 0; i < 4; i++) ctxa[j][i] = 0.0f;
    float zr0 = 0.0f, zr1 = 0.0f;

    const uint32_t kh_base = sb + SM_KH + kw * CHUNKB;
    const uint32_t vh_base = sb + SM_VH + kw * CHUNKB;

    for (int ph = 0; ph < 4; ph++) {
        __syncthreads();   // K/V buffers free (also covers Z/Q init on ph=0)

        // load K,V rows [ph*256, ph*256+256) into 4 slots, hi/lo split
        #pragma unroll
        for (int it = 0; it < 8; it++) {
            int u = tid + it * 512;       // 4096 units
            int rp = u >> 4, dg = u & 15;
            int slot = rp >> 6, r = rp & 63;
            size_t grow = (size_t)(ph * 256 + rp) * 64 + dg * 4;
            float4 kv = *(const float4*)(Kb + grow);
            split_store(sm, SM_KH + slot * CHUNKB, SM_KL + slot * CHUNKB, r, dg, kv);
            float4 vv = *(const float4*)(Vb + grow);
            split_store(sm, SM_VH + slot * CHUNKB, SM_VL + slot * CHUNKB, r, dg, vv);
        }
        __syncthreads();

        const int c = ph * 4 + kw;        // this warp's chunk (64 K-cols)

        // ---------- GEMM1: S = Q' @ Kc^T (m16 x n64 x k64, 3 products) ----------
        float S[8][4];
        #pragma unroll
        for (int j = 0; j < 8; j++)
            #pragma unroll
            for (int i = 0; i < 4; i++) S[j][i] = 0.0f;

        #pragma unroll
        for (int kk = 0; kk < 4; kk++) {
            uint32_t arow = (uint32_t)(mh * 16 + (lane & 15)) * PITCHB
                          + (uint32_t)(kk * 16 + 8 * ((lane >> 4) & 1)) * 2;
            uint32_t Ah[4], Al[4];
            ldsm_x4(sb + SM_QH + arow, Ah);
            ldsm_x4(sb + SM_QL + arow, Al);
            uint32_t brc = (uint32_t)(lane & 7) * PITCHB
                         + (uint32_t)(kk * 16 + 8 * ((lane >> 3) & 1)) * 2;
            #pragma unroll
            for (int j = 0; j < 8; j++) {
                uint32_t ba = kh_base + (uint32_t)(j * 8) * PITCHB + brc;
                uint32_t Bh[2], Bl[2];
                ldsm_x2(ba, Bh);
                ldsm_x2(ba + 4 * CHUNKB, Bl);    // KL region
                mma_bf16(S[j], Ah, Bh);
                mma_bf16(S[j], Ah, Bl);
                mma_bf16(S[j], Al, Bh);
            }
        }

        // ---------- epilogue: mask, exp, unnorm attn STG, pack P hi/lo ----------
        uint32_t Ph0[8], Ph1[8], Pl0[8], Pl1[8];
        #pragma unroll
        for (int j = 0; j < 8; j++) {
            int col = c * 64 + j * 8 + 2 * t;
            uint2 m0 = *(const uint2*)(Mb + (size_t)r0 * 1024 + col);
            uint2 m1 = *(const uint2*)(Mb + (size_t)r1 * 1024 + col);
            float p00 = m0.x ? 0.0f : __expf(S[j][0]);
            float p01 = m0.y ? 0.0f : __expf(S[j][1]);
            float p10 = m1.x ? 0.0f : __expf(S[j][2]);
            float p11 = m1.y ? 0.0f : __expf(S[j][3]);
            zr0 += p00 + p01;
            zr1 += p10 + p11;
            *(float2*)(attnb + (size_t)r0 * 1024 + col) = make_float2(p00, p01);
            *(float2*)(attnb + (size_t)r1 * 1024 + col) = make_float2(p10, p11);
            __nv_bfloat162 h0 = __floats2bfloat162_rn(p00, p01);
            __nv_bfloat162 l0 = __floats2bfloat162_rn(p00 - __low2float(h0), p01 - __high2float(h0));
            __nv_bfloat162 h1 = __floats2bfloat162_rn(p10, p11);
            __nv_bfloat162 l1 = __floats2bfloat162_rn(p10 - __low2float(h1), p11 - __high2float(h1));
            Ph0[j] = b2u(h0); Pl0[j] = b2u(l0);
            Ph1[j] = b2u(h1); Pl1[j] = b2u(l1);
        }

        // ---------- GEMM2: ctx += P @ Vc (m16 x n64 x k64, 3 products) ----------
        #pragma unroll
        for (int s = 0; s < 4; s++) {
            uint32_t Ahf[4] = { Ph0[2 * s], Ph1[2 * s], Ph0[2 * s + 1], Ph1[2 * s + 1] };
            uint32_t Alf[4] = { Pl0[2 * s], Pl1[2 * s], Pl0[2 * s + 1], Pl1[2 * s + 1] };
            uint32_t vrc = (uint32_t)(s * 16 + (lane & 7) + 8 * ((lane >> 3) & 1)) * PITCHB;
            #pragma unroll
            for (int j = 0; j < 8; j++) {
                uint32_t va = vh_base + vrc + (uint32_t)(j * 16);
                uint32_t Bh[2], Bl[2];
                ldsm_x2t(va, Bh);
                ldsm_x2t(va + 4 * CHUNKB, Bl);   // VL region
                mma_bf16(ctxa[j], Ahf, Bh);
                mma_bf16(ctxa[j], Ahf, Bl);
                mma_bf16(ctxa[j], Alf, Bh);
            }
        }
    }

    // ---- Z: quad-reduce then smem atomic ----
    zr0 += __shfl_xor_sync(0xFFFFFFFFu, zr0, 1);
    zr0 += __shfl_xor_sync(0xFFFFFFFFu, zr0, 2);
    zr1 += __shfl_xor_sync(0xFFFFFFFFu, zr1, 1);
    zr1 += __shfl_xor_sync(0xFFFFFFFFu, zr1, 2);
    if (t == 0) {
        atomicAdd((float*)(sm + SM_Z) + r0, zr0);
        atomicAdd((float*)(sm + SM_Z) + r1, zr1);
    }
    __syncthreads();

    if (tid < 64)
        ((float*)(sm + SM_INVZ))[tid] = 1.0f / ((float*)(sm + SM_Z))[tid];
    float* sc = (float*)(sm + SM_CTX);
    #pragma unroll
    for (int it = 0; it < 8; it++) sc[tid + it * 512] = 0.0f;
    __syncthreads();

    // ---- ctx cross-warp reduce (k quadrants) ----
    #pragma unroll
    for (int j = 0; j < 8; j++) {
        int cb = j * 8 + 2 * t;
        atomicAdd(&sc[r0 * 64 + cb],     ctxa[j][0]);
        atomicAdd(&sc[r0 * 64 + cb + 1], ctxa[j][1]);
        atomicAdd(&sc[r1 * 64 + cb],     ctxa[j][2]);
        atomicAdd(&sc[r1 * 64 + cb + 1], ctxa[j][3]);
    }
    __syncthreads();

    // ---- store ctx (scaled) ----
    const float* inv = (const float*)(sm + SM_INVZ);
    #pragma unroll
    for (int it = 0; it < 8; it++) {
        int u = tid + it * 512;           // 4096
        int r = u >> 6;
        ctxb[(size_t)(r) * 64 + (u & 63)] = sc[u] * inv[r];
    }

    // ---- rescale attn tile (L2-hot) ----
    #pragma unroll 4
    for (int it = 0; it < 32; it++) {
        int u = tid + it * 512;           // 16384 float4
        int r = u >> 8;
        float iz = inv[r];
        float4* p = (float4*)(attnb + (size_t)r * 1024) + (u & 255);
        float4 v = *p;
        v.x *= iz; v.y *= iz; v.z *= iz; v.w *= iz;
        *p = v;
    }
}

extern "C" void kernel_launch(void* const* d_in, const int* in_sizes, int n_in,
                              void* d_out, int out_size) {
    const float* q = (const float*)d_in[0];
    const float* k = (const float*)d_in[1];
    const float* v = (const float*)d_in[2];
    const uint32_t* m = (const uint32_t*)d_in[3];

    float* ctx  = (float*)d_out;
    float* attn = (float*)d_out + 32 * 1024 * 64;

    cudaFuncSetAttribute(sdpa_mma_kernel, cudaFuncAttributeMaxDynamicSharedMemorySize,
                         SM_TOTAL);

    dim3 grid(16, 32);   // (q tiles of 64, batch)
    sdpa_mma_kernel<<<grid, 512, SM_TOTAL>>>(q, k, v, m, ctx, attn);
}

// round 10
// speedup vs baseline: 2.0878x; 1.4758x over previous
#include <cuda_runtime.h>
#include <cuda_bf16.h>
#include <cstdint>

// SDPA via mma.sync bf16 hi/lo (3 products). cp.async double-buffered f32 K/V.
// B=32, Q=K=1024, D=64 fp32. out = [context | attn]. mask 4B, nonzero => p=0.
// CTA: 64 q rows, 512 thr = 16 warps = (mh 0..3) x (kw 0..3).
// 8 phases x 128 K-rows; warp kw handles 32 K-cols per phase.

#define PITCHB 144            // Q bf16 smem pitch (bytes)
#define PITCHF 68             // f32 staging pitch (floats)
#define KROWB  272            // PITCHF*4 bytes
#define STAGE_T 34816         // 128 rows * 272 B
#define STAGE_B (2 * STAGE_T) // K+V per buffer

#define SM_QH   0
#define SM_QL   9216
#define SM_KF   18432                    // 2 bufs of STAGE_B
#define SM_Z    (SM_KF + 2 * STAGE_B)    // 157696
#define SM_INVZ (SM_Z + 256)
#define SM_CTX  (SM_INVZ + 256)
#define SM_TOTAL (SM_CTX + 16384)        // 174592 B

__device__ __forceinline__ uint32_t smem_u32(const void* p) {
    uint32_t a;
    asm("{ .reg .u64 t; cvta.to.shared.u64 t, %1; cvt.u32.u64 %0, t; }" : "=r"(a) : "l"(p));
    return a;
}
__device__ __forceinline__ uint32_t b2u(__nv_bfloat162 h) { return *(uint32_t*)&h; }

__device__ __forceinline__ void ldsm_x4(uint32_t a, uint32_t r[4]) {
    asm volatile("ldmatrix.sync.aligned.m8n8.x4.shared.b16 {%0,%1,%2,%3}, [%4];"
                 : "=r"(r[0]), "=r"(r[1]), "=r"(r[2]), "=r"(r[3]) : "r"(a));
}
__device__ __forceinline__ void mma_bf16(float c[4], const uint32_t a[4], const uint32_t b[2]) {
    asm volatile("mma.sync.aligned.m16n8k16.row.col.f32.bf16.bf16.f32 "
                 "{%0,%1,%2,%3}, {%4,%5,%6,%7}, {%8,%9}, {%0,%1,%2,%3};"
                 : "+f"(c[0]), "+f"(c[1]), "+f"(c[2]), "+f"(c[3])
                 : "r"(a[0]), "r"(a[1]), "r"(a[2]), "r"(a[3]), "r"(b[0]), "r"(b[1]));
}
#define CP16(dst, src) \
    asm volatile("cp.async.cg.shared.global [%0], [%1], 16;" \
                 :: "r"(dst), "l"(__cvta_generic_to_global(src)) : "memory")

// split two floats -> bf16x2 hi and lo words
__device__ __forceinline__ void split2(float a, float b, uint32_t& h, uint32_t& l) {
    __nv_bfloat162 hh = __floats2bfloat162_rn(a, b);
    __nv_bfloat162 ll = __floats2bfloat162_rn(a - __low2float(hh), b - __high2float(hh));
    h = b2u(hh); l = b2u(ll);
}

__global__ __launch_bounds__(512, 1)
void sdpa_mma_kernel(const float* __restrict__ Qg, const float* __restrict__ Kg,
                     const float* __restrict__ Vg, const uint32_t* __restrict__ Mg,
                     float* __restrict__ ctx, float* __restrict__ attn)
{
    extern __shared__ char sm[];
    const uint32_t sb = smem_u32(sm);

    const int tid  = threadIdx.x;
    const int wid  = tid >> 5;
    const int lane = tid & 31;
    const int g    = lane >> 2;
    const int t    = lane & 3;
    const int mh   = wid & 3;         // m16 row group
    const int kw   = wid >> 2;        // 32-col k quadrant within phase

    const int b  = blockIdx.y;
    const int q0 = blockIdx.x * 64;

    const float* Qb = Qg + ((size_t)b * 1024 + q0) * 64;
    const float* Kb = Kg + (size_t)b * 1024 * 64;
    const float* Vb = Vg + (size_t)b * 1024 * 64;
    const uint32_t* Mb = Mg + ((size_t)b * 1024 + q0) * 1024;
    float* attnb = attn + ((size_t)b * 1024 + q0) * 1024;
    float* ctxb  = ctx  + ((size_t)b * 1024 + q0) * 64;

    const int r0 = mh * 16 + g;
    const int r1 = r0 + 8;

    // ---- issue phase-0 cp.async (K,V f32 -> staging buf 0) ----
    {
        #pragma unroll
        for (int it = 0; it < 4; it++) {
            int u = tid + it * 512;              // 2048 units
            int row = u >> 4, sg = u & 15;
            uint32_t kd = sb + SM_KF + (uint32_t)(row * KROWB + sg * 16);
            CP16(kd, Kb + (size_t)row * 64 + sg * 4);
            CP16(kd + STAGE_T, Vb + (size_t)row * 64 + sg * 4);
        }
        asm volatile("cp.async.commit_group;" ::: "memory");
    }

    // ---- Q (64x64) * 0.125, split hi/lo bf16 into pitched smem ----
    if (tid < 64) ((float*)(sm + SM_Z))[tid] = 0.0f;
    #pragma unroll
    for (int it = 0; it < 2; it++) {
        int u = tid + it * 512;
        int r = u >> 4, dg = u & 15;
        float4 v = *(const float4*)(Qb + (size_t)r * 64 + dg * 4);
        v.x *= 0.125f; v.y *= 0.125f; v.z *= 0.125f; v.w *= 0.125f;
        uint32_t h01, l01, h23, l23;
        split2(v.x, v.y, h01, l01);
        split2(v.z, v.w, h23, l23);
        int off = r * PITCHB + dg * 8;
        *(uint2*)(sm + SM_QH + off) = make_uint2(h01, h23);
        *(uint2*)(sm + SM_QL + off) = make_uint2(l01, l23);
    }
    __syncthreads();

    // ---- hoist Q fragments (reused all 8 phases) ----
    uint32_t QAh[4][4], QAl[4][4];
    #pragma unroll
    for (int kk = 0; kk < 4; kk++) {
        uint32_t arow = (uint32_t)(mh * 16 + (lane & 15)) * PITCHB
                      + (uint32_t)(kk * 16 + 8 * ((lane >> 4) & 1)) * 2;
        ldsm_x4(sb + SM_QH + arow, QAh[kk]);
        ldsm_x4(sb + SM_QL + arow, QAl[kk]);
    }

    float ctxa[8][4];
    #pragma unroll
    for (int j = 0; j < 8; j++)
        #pragma unroll
        for (int i = 0; i < 4; i++) ctxa[j][i] = 0.0f;
    float zr0 = 0.0f, zr1 = 0.0f;

    for (int ph = 0; ph < 8; ph++) {
        // prefetch next phase
        if (ph < 7) {
            int nb = (ph + 1) & 1;
            #pragma unroll
            for (int it = 0; it < 4; it++) {
                int u = tid + it * 512;
                int row = u >> 4, sg = u & 15;
                uint32_t kd = sb + SM_KF + (uint32_t)(nb * STAGE_B + row * KROWB + sg * 16);
                CP16(kd, Kb + (size_t)((ph + 1) * 128 + row) * 64 + sg * 4);
                CP16(kd + STAGE_T, Vb + (size_t)((ph + 1) * 128 + row) * 64 + sg * 4);
            }
            asm volatile("cp.async.commit_group;" ::: "memory");
            asm volatile("cp.async.wait_group 1;" ::: "memory");
        } else {
            asm volatile("cp.async.wait_group 0;" ::: "memory");
        }
        __syncthreads();

        const int buf = ph & 1;
        const float* Kf = (const float*)(sm + SM_KF + buf * STAGE_B);
        const float* Vf = (const float*)(sm + SM_KF + buf * STAGE_B + STAGE_T);

        // ---------- GEMM1: S(m16 x n32) = Q' @ Kc^T over k=64 ----------
        float S[4][4];
        #pragma unroll
        for (int j = 0; j < 4; j++)
            #pragma unroll
            for (int i = 0; i < 4; i++) S[j][i] = 0.0f;

        #pragma unroll
        for (int kk = 0; kk < 4; kk++) {
            #pragma unroll
            for (int j = 0; j < 4; j++) {
                const float* kr = Kf + (kw * 32 + j * 8 + (lane >> 2)) * PITCHF + kk * 16 + 2 * t;
                float2 x = *(const float2*)(kr);
                float2 y = *(const float2*)(kr + 8);
                uint32_t Bh[2], Bl[2];
                split2(x.x, x.y, Bh[0], Bl[0]);
                split2(y.x, y.y, Bh[1], Bl[1]);
                mma_bf16(S[j], QAh[kk], Bh);
                mma_bf16(S[j], QAh[kk], Bl);
                mma_bf16(S[j], QAl[kk], Bh);
            }
        }

        // ---------- epilogue: mask, exp, unnorm attn, pack P ----------
        uint32_t Ph0[4], Ph1[4], Pl0[4], Pl1[4];
        #pragma unroll
        for (int j = 0; j < 4; j++) {
            int col = ph * 128 + kw * 32 + j * 8 + 2 * t;
            uint2 m0 = *(const uint2*)(Mb + (size_t)r0 * 1024 + col);
            uint2 m1 = *(const uint2*)(Mb + (size_t)r1 * 1024 + col);
            float p00 = m0.x ? 0.0f : __expf(S[j][0]);
            float p01 = m0.y ? 0.0f : __expf(S[j][1]);
            float p10 = m1.x ? 0.0f : __expf(S[j][2]);
            float p11 = m1.y ? 0.0f : __expf(S[j][3]);
            zr0 += p00 + p01;
            zr1 += p10 + p11;
            *(float2*)(attnb + (size_t)r0 * 1024 + col) = make_float2(p00, p01);
            *(float2*)(attnb + (size_t)r1 * 1024 + col) = make_float2(p10, p11);
            split2(p00, p01, Ph0[j], Pl0[j]);
            split2(p10, p11, Ph1[j], Pl1[j]);
        }

        // ---------- GEMM2: ctx += P(m16 x k32) @ Vc(k32 x n64) ----------
        #pragma unroll
        for (int s = 0; s < 2; s++) {
            uint32_t Ahf[4] = { Ph0[2 * s], Ph1[2 * s], Ph0[2 * s + 1], Ph1[2 * s + 1] };
            uint32_t Alf[4] = { Pl0[2 * s], Pl1[2 * s], Pl0[2 * s + 1], Pl1[2 * s + 1] };
            const int kb = kw * 32 + s * 16 + 2 * t;
            #pragma unroll
            for (int j2 = 0; j2 < 8; j2++) {
                const int d = j2 * 8 + (lane >> 2);
                float v0 = Vf[(kb + 0) * PITCHF + d];
                float v1 = Vf[(kb + 1) * PITCHF + d];
                float v2 = Vf[(kb + 8) * PITCHF + d];
                float v3 = Vf[(kb + 9) * PITCHF + d];
                uint32_t Bh[2], Bl[2];
                split2(v0, v1, Bh[0], Bl[0]);
                split2(v2, v3, Bh[1], Bl[1]);
                mma_bf16(ctxa[j2], Ahf, Bh);
                mma_bf16(ctxa[j2], Ahf, Bl);
                mma_bf16(ctxa[j2], Alf, Bh);
            }
        }
        __syncthreads();   // staging buffer reuse safety
    }

    // ---- Z: quad-reduce then smem atomic ----
    zr0 += __shfl_xor_sync(0xFFFFFFFFu, zr0, 1);
    zr0 += __shfl_xor_sync(0xFFFFFFFFu, zr0, 2);
    zr1 += __shfl_xor_sync(0xFFFFFFFFu, zr1, 1);
    zr1 += __shfl_xor_sync(0xFFFFFFFFu, zr1, 2);
    if (t == 0) {
        atomicAdd((float*)(sm + SM_Z) + r0, zr0);
        atomicAdd((float*)(sm + SM_Z) + r1, zr1);
    }
    __syncthreads();

    if (tid < 64)
        ((float*)(sm + SM_INVZ))[tid] = 1.0f / ((float*)(sm + SM_Z))[tid];
    float* sc = (float*)(sm + SM_CTX);
    #pragma unroll
    for (int it = 0; it < 8; it++) sc[tid + it * 512] = 0.0f;
    __syncthreads();

    // ---- ctx cross-warp reduce (k quadrants) ----
    #pragma unroll
    for (int j = 0; j < 8; j++) {
        int cb = j * 8 + 2 * t;
        atomicAdd(&sc[r0 * 64 + cb],     ctxa[j][0]);
        atomicAdd(&sc[r0 * 64 + cb + 1], ctxa[j][1]);
        atomicAdd(&sc[r1 * 64 + cb],     ctxa[j][2]);
        atomicAdd(&sc[r1 * 64 + cb + 1], ctxa[j][3]);
    }
    __syncthreads();

    // ---- store ctx (scaled) ----
    const float* inv = (const float*)(sm + SM_INVZ);
    #pragma unroll
    for (int it = 0; it < 8; it++) {
        int u = tid + it * 512;
        int r = u >> 6;
        ctxb[(size_t)r * 64 + (u & 63)] = sc[u] * inv[r];
    }

    // ---- rescale attn tile (L2-hot) ----
    #pragma unroll 4
    for (int it = 0; it < 32; it++) {
        int u = tid + it * 512;
        int r = u >> 8;
        float iz = inv[r];
        float4* p = (float4*)(attnb + (size_t)r * 1024) + (u & 255);
        float4 v = *p;
        v.x *= iz; v.y *= iz; v.z *= iz; v.w *= iz;
        *p = v;
    }
}

extern "C" void kernel_launch(void* const* d_in, const int* in_sizes, int n_in,
                              void* d_out, int out_size) {
    const float* q = (const float*)d_in[0];
    const float* k = (const float*)d_in[1];
    const float* v = (const float*)d_in[2];
    const uint32_t* m = (const uint32_t*)d_in[3];

    float* ctx  = (float*)d_out;
    float* attn = (float*)d_out + 32 * 1024 * 64;

    cudaFuncSetAttribute(sdpa_mma_kernel, cudaFuncAttributeMaxDynamicSharedMemorySize,
                         SM_TOTAL);

    dim3 grid(16, 32);   // (q tiles of 64, batch)
    sdpa_mma_kernel<<<grid, 512, SM_TOTAL>>>(q, k, v, m, ctx, attn);
}

// round 12
// speedup vs baseline: 2.1384x; 1.0242x over previous
#include <cuda_runtime.h>
#include <cuda_bf16.h>
#include <cstdint>

// SDPA via mma.sync bf16 hi/lo (3 products ~ fp32). cp.async f32 staging +
// single shared convert pass per phase + ldmatrix fragments.
// B=32, Q=K=1024, D=64 fp32. out = [context | attn]. mask 4B, nonzero => p=0.
// CTA: 64 q rows, 512 thr = 16 warps = (mh 0..3 m-rowgroup) x (kw 0..3 k/n-quadrant).
// 16 phases x 64 K-rows; warp kw owns 16 K-cols (GEMM1 n) / 16 K-rows (GEMM2 k).

#define PITCHB 144            // bf16 tile row pitch (bytes), R7-validated
#define TILEB  (64 * PITCHB)  // 9216 B: one 64-row bf16 tile
#define STG_T  16384          // 64 rows * 256 B (f32, pitch 64 floats)
#define STG_B  (2 * STG_T)    // K + V per staging buffer

#define SM_QH   0
#define SM_QL   (SM_QH + TILEB)
#define SM_KH   (SM_QL + TILEB)
#define SM_KL   (SM_KH + TILEB)
#define SM_VH   (SM_KL + TILEB)
#define SM_VL   (SM_VH + TILEB)
#define SM_STG  (SM_VL + TILEB)          // 2 bufs of STG_B = 65536
#define SM_Z    (SM_STG + 2 * STG_B)
#define SM_INVZ (SM_Z + 256)
#define SM_CTX  (SM_INVZ + 256)
#define SM_TOTAL (SM_CTX + 16384)        // 137728 B

__device__ __forceinline__ uint32_t smem_u32(const void* p) {
    uint32_t a;
    asm("{ .reg .u64 t; cvta.to.shared.u64 t, %1; cvt.u32.u64 %0, t; }" : "=r"(a) : "l"(p));
    return a;
}
__device__ __forceinline__ uint32_t b2u(__nv_bfloat162 h) { return *(uint32_t*)&h; }

__device__ __forceinline__ void ldsm_x4(uint32_t a, uint32_t r[4]) {
    asm volatile("ldmatrix.sync.aligned.m8n8.x4.shared.b16 {%0,%1,%2,%3}, [%4];"
                 : "=r"(r[0]), "=r"(r[1]), "=r"(r[2]), "=r"(r[3]) : "r"(a));
}
__device__ __forceinline__ void ldsm_x2t(uint32_t a, uint32_t r[2]) {
    asm volatile("ldmatrix.sync.aligned.m8n8.x2.trans.shared.b16 {%0,%1}, [%2];"
                 : "=r"(r[0]), "=r"(r[1]) : "r"(a));
}
__device__ __forceinline__ void mma_bf16(float c[4], const uint32_t a[4], const uint32_t b[2]) {
    asm volatile("mma.sync.aligned.m16n8k16.row.col.f32.bf16.bf16.f32 "
                 "{%0,%1,%2,%3}, {%4,%5,%6,%7}, {%8,%9}, {%0,%1,%2,%3};"
                 : "+f"(c[0]), "+f"(c[1]), "+f"(c[2]), "+f"(c[3])
                 : "r"(a[0]), "r"(a[1]), "r"(a[2]), "r"(a[3]), "r"(b[0]), "r"(b[1]));
}
#define CP16(dst, src) \
    asm volatile("cp.async.cg.shared.global [%0], [%1], 16;" \
                 :: "r"(dst), "l"(__cvta_generic_to_global(src)) : "memory")

__device__ __forceinline__ void split2(float a, float b, uint32_t& h, uint32_t& l) {
    __nv_bfloat162 hh = __floats2bfloat162_rn(a, b);
    __nv_bfloat162 ll = __floats2bfloat162_rn(a - __low2float(hh), b - __high2float(hh));
    h = b2u(hh); l = b2u(ll);
}

__global__ __launch_bounds__(512, 1)
void sdpa_mma_kernel(const float* __restrict__ Qg, const float* __restrict__ Kg,
                     const float* __restrict__ Vg, const uint32_t* __restrict__ Mg,
                     float* __restrict__ ctx, float* __restrict__ attn)
{
    extern __shared__ char sm[];
    const uint32_t sb = smem_u32(sm);

    const int tid  = threadIdx.x;
    const int wid  = tid >> 5;
    const int lane = tid & 31;
    const int g    = lane >> 2;
    const int t    = lane & 3;
    const int mh   = wid & 3;
    const int kw   = wid >> 2;

    const int b  = blockIdx.y;
    const int q0 = blockIdx.x * 64;

    const float* Qb = Qg + ((size_t)b * 1024 + q0) * 64;
    const float* Kb = Kg + (size_t)b * 1024 * 64;
    const float* Vb = Vg + (size_t)b * 1024 * 64;
    const uint32_t* Mb = Mg + ((size_t)b * 1024 + q0) * 1024;
    float* attnb = attn + ((size_t)b * 1024 + q0) * 1024;
    float* ctxb  = ctx  + ((size_t)b * 1024 + q0) * 64;

    const int r0 = mh * 16 + g;
    const int r1 = r0 + 8;

    // ---- issue phase-0 staging (K,V rows 0..63 f32) ----
    {
        #pragma unroll
        for (int it = 0; it < 2; it++) {
            int u = tid + it * 512;          // 1024 units
            int row = u >> 4, sg = u & 15;
            uint32_t kd = sb + SM_STG + (uint32_t)(row * 256 + sg * 16);
            CP16(kd, Kb + (size_t)row * 64 + sg * 4);
            CP16(kd + STG_T, Vb + (size_t)row * 64 + sg * 4);
        }
        asm volatile("cp.async.commit_group;" ::: "memory");
    }

    // ---- Q (64x64) * 0.125, split hi/lo bf16 ----
    if (tid < 64) ((float*)(sm + SM_Z))[tid] = 0.0f;
    #pragma unroll
    for (int it = 0; it < 2; it++) {
        int u = tid + it * 512;
        int r = u >> 4, dg = u & 15;
        float4 v = *(const float4*)(Qb + (size_t)r * 64 + dg * 4);
        v.x *= 0.125f; v.y *= 0.125f; v.z *= 0.125f; v.w *= 0.125f;
        uint32_t h01, l01, h23, l23;
        split2(v.x, v.y, h01, l01);
        split2(v.z, v.w, h23, l23);
        int off = r * PITCHB + dg * 8;
        *(uint2*)(sm + SM_QH + off) = make_uint2(h01, h23);
        *(uint2*)(sm + SM_QL + off) = make_uint2(l01, l23);
    }
    __syncthreads();

    // ---- hoist Q fragments (reused all phases) ----
    uint32_t QAh[4][4], QAl[4][4];
    #pragma unroll
    for (int kk = 0; kk < 4; kk++) {
        uint32_t arow = (uint32_t)(mh * 16 + (lane & 15)) * PITCHB
                      + (uint32_t)(kk * 16 + 8 * ((lane >> 4) & 1)) * 2;
        ldsm_x4(sb + SM_QH + arow, QAh[kk]);
        ldsm_x4(sb + SM_QL + arow, QAl[kk]);
    }

    float ctxa[8][4];
    #pragma unroll
    for (int j = 0; j < 8; j++)
        #pragma unroll
        for (int i = 0; i < 4; i++) ctxa[j][i] = 0.0f;
    float zr0 = 0.0f, zr1 = 0.0f;

    // precomputed fragment addresses
    const uint32_t kfrag_base = sb + SM_KH + (uint32_t)kw * 16 * PITCHB
        + (uint32_t)((lane & 7) + 8 * ((lane >> 4) & 1)) * PITCHB
        + (uint32_t)(8 * ((lane >> 3) & 1)) * 2;
    const uint32_t vfrag_base = sb + SM_VH
        + (uint32_t)(kw * 16 + (lane & 7) + 8 * ((lane >> 3) & 1)) * PITCHB;

    for (int ph = 0; ph < 16; ph++) {
        // prefetch next phase staging
        if (ph < 15) {
            int nb = (ph + 1) & 1;
            #pragma unroll
            for (int it = 0; it < 2; it++) {
                int u = tid + it * 512;
                int row = u >> 4, sg = u & 15;
                uint32_t kd = sb + SM_STG + (uint32_t)(nb * STG_B + row * 256 + sg * 16);
                CP16(kd, Kb + (size_t)((ph + 1) * 64 + row) * 64 + sg * 4);
                CP16(kd + STG_T, Vb + (size_t)((ph + 1) * 64 + row) * 64 + sg * 4);
            }
            asm volatile("cp.async.commit_group;" ::: "memory");
            asm volatile("cp.async.wait_group 1;" ::: "memory");
        } else {
            asm volatile("cp.async.wait_group 0;" ::: "memory");
        }
        __syncthreads();

        // ---- shared convert: f32 staging -> bf16 hi/lo tiles (once) ----
        {
            const int buf = ph & 1;
            const float* Kf = (const float*)(sm + SM_STG + buf * STG_B);
            const float* Vf = Kf + STG_T / 4;
            #pragma unroll
            for (int it = 0; it < 2; it++) {
                int u = tid + it * 512;
                int r = u >> 4, dg = u & 15;
                int off = r * PITCHB + dg * 8;
                float4 kv = *(const float4*)(Kf + r * 64 + dg * 4);
                uint32_t h01, l01, h23, l23;
                split2(kv.x, kv.y, h01, l01);
                split2(kv.z, kv.w, h23, l23);
                *(uint2*)(sm + SM_KH + off) = make_uint2(h01, h23);
                *(uint2*)(sm + SM_KL + off) = make_uint2(l01, l23);
                float4 vv = *(const float4*)(Vf + r * 64 + dg * 4);
                split2(vv.x, vv.y, h01, l01);
                split2(vv.z, vv.w, h23, l23);
                *(uint2*)(sm + SM_VH + off) = make_uint2(h01, h23);
                *(uint2*)(sm + SM_VL + off) = make_uint2(l01, l23);
            }
        }
        __syncthreads();

        // ---- GEMM1: S(m16 x n16) = Q' @ Kc^T over k=64, 3 products ----
        float S[2][4];
        #pragma unroll
        for (int j = 0; j < 2; j++)
            #pragma unroll
            for (int i = 0; i < 4; i++) S[j][i] = 0.0f;

        #pragma unroll
        for (int kk = 0; kk < 4; kk++) {
            uint32_t ba = kfrag_base + (uint32_t)(kk * 16) * 2;
            uint32_t Bh[4], Bl[4];
            ldsm_x4(ba, Bh);
            ldsm_x4(ba + (SM_KL - SM_KH), Bl);
            mma_bf16(S[0], QAh[kk], Bh);
            mma_bf16(S[0], QAh[kk], Bl);
            mma_bf16(S[0], QAl[kk], Bh);
            uint32_t Bh1[2] = { Bh[2], Bh[3] };
            uint32_t Bl1[2] = { Bl[2], Bl[3] };
            mma_bf16(S[1], QAh[kk], Bh1);
            mma_bf16(S[1], QAh[kk], Bl1);
            mma_bf16(S[1], QAl[kk], Bh1);
        }

        // ---- epilogue: mask, exp, unnorm attn, pack P hi/lo ----
        uint32_t Ph0[2], Ph1[2], Pl0[2], Pl1[2];
        #pragma unroll
        for (int j = 0; j < 2; j++) {
            int col = ph * 64 + kw * 16 + j * 8 + 2 * t;
            uint2 m0 = *(const uint2*)(Mb + (size_t)r0 * 1024 + col);
            uint2 m1 = *(const uint2*)(Mb + (size_t)r1 * 1024 + col);
            float p00 = m0.x ? 0.0f : __expf(S[j][0]);
            float p01 = m0.y ? 0.0f : __expf(S[j][1]);
            float p10 = m1.x ? 0.0f : __expf(S[j][2]);
            float p11 = m1.y ? 0.0f : __expf(S[j][3]);
            zr0 += p00 + p01;
            zr1 += p10 + p11;
            *(float2*)(attnb + (size_t)r0 * 1024 + col) = make_float2(p00, p01);
            *(float2*)(attnb + (size_t)r1 * 1024 + col) = make_float2(p10, p11);
            split2(p00, p01, Ph0[j], Pl0[j]);
            split2(p10, p11, Ph1[j], Pl1[j]);
        }

        // ---- GEMM2: ctx += P(m16 x k16) @ Vc(k16 x n64), 3 products ----
        {
            uint32_t Ahf[4] = { Ph0[0], Ph1[0], Ph0[1], Ph1[1] };
            uint32_t Alf[4] = { Pl0[0], Pl1[0], Pl0[1], Pl1[1] };
            #pragma unroll
            for (int j2 = 0; j2 < 8; j2++) {
                uint32_t va = vfrag_base + (uint32_t)(j2 * 16);
                uint32_t Bh[2], Bl[2];
                ldsm_x2t(va, Bh);
                ldsm_x2t(va + (SM_VL - SM_VH), Bl);
                mma_bf16(ctxa[j2], Ahf, Bh);
                mma_bf16(ctxa[j2], Ahf, Bl);
                mma_bf16(ctxa[j2], Alf, Bh);
            }
        }
        __syncthreads();   // protect bf16 tiles before next convert
    }

    // ---- Z: quad-reduce then smem atomic ----
    zr0 += __shfl_xor_sync(0xFFFFFFFFu, zr0, 1);
    zr0 += __shfl_xor_sync(0xFFFFFFFFu, zr0, 2);
    zr1 += __shfl_xor_sync(0xFFFFFFFFu, zr1, 1);
    zr1 += __shfl_xor_sync(0xFFFFFFFFu, zr1, 2);
    if (t == 0) {
        atomicAdd((float*)(sm + SM_Z) + r0, zr0);
        atomicAdd((float*)(sm + SM_Z) + r1, zr1);
    }
    __syncthreads();

    if (tid < 64)
        ((float*)(sm + SM_INVZ))[tid] = 1.0f / ((float*)(sm + SM_Z))[tid];
    float* sc = (float*)(sm + SM_CTX);
    #pragma unroll
    for (int it = 0; it < 8; it++) sc[tid + it * 512] = 0.0f;
    __syncthreads();

    // ---- ctx cross-warp reduce (k quadrants) ----
    #pragma unroll
    for (int j = 0; j < 8; j++) {
        int cb = j * 8 + 2 * t;
        atomicAdd(&sc[r0 * 64 + cb],     ctxa[j][0]);
        atomicAdd(&sc[r0 * 64 + cb + 1], ctxa[j][1]);
        atomicAdd(&sc[r1 * 64 + cb],     ctxa[j][2]);
        atomicAdd(&sc[r1 * 64 + cb + 1], ctxa[j][3]);
    }
    __syncthreads();

    // ---- store ctx (scaled) ----
    const float* inv = (const float*)(sm + SM_INVZ);
    #pragma unroll
    for (int it = 0; it < 8; it++) {
        int u = tid + it * 512;
        int r = u >> 6;
        ctxb[(size_t)r * 64 + (u & 63)] = sc[u] * inv[r];
    }

    // ---- rescale attn tile (L2-hot) ----
    #pragma unroll 4
    for (int it = 0; it < 32; it++) {
        int u = tid + it * 512;
        int r = u >> 8;
        float iz = inv[r];
        float4* p = (float4*)(attnb + (size_t)r * 1024) + (u & 255);
        float4 v = *p;
        v.x *= iz; v.y *= iz; v.z *= iz; v.w *= iz;
        *p = v;
    }
}

extern "C" void kernel_launch(void* const* d_in, const int* in_sizes, int n_in,
                              void* d_out, int out_size) {
    const float* q = (const float*)d_in[0];
    const float* k = (const float*)d_in[1];
    const float* v = (const float*)d_in[2];
    const uint32_t* m = (const uint32_t*)d_in[3];

    float* ctx  = (float*)d_out;
    float* attn = (float*)d_out + 32 * 1024 * 64;

    cudaFuncSetAttribute(sdpa_mma_kernel, cudaFuncAttributeMaxDynamicSharedMemorySize,
                         SM_TOTAL);

    dim3 grid(16, 32);   // (q tiles of 64, batch)
    sdpa_mma_kernel<<<grid, 512, SM_TOTAL>>>(q, k, v, m, ctx, attn);
}

// round 14
// speedup vs baseline: 2.6861x; 1.2562x over previous
#include <cuda_runtime.h>
#include <cuda_bf16.h>
#include <cstdint>

// SDPA via mma.sync bf16 hi/lo (3 products ~ fp32 accuracy).
// 256-thread CTAs, 2 CTAs/SM (register-exact). cp.async single-buffer K/V f32
// staging with early reissue + double-buffered mask staging + shared convert.
// B=32, Q=K=1024, D=64 fp32. out = [context | attn]. mask 4B, nonzero => p=0.
// CTA: 32 q rows, 8 warps = (mh 0..1 m16-rowgroup) x (kw 0..3 n/k-quadrant).
// 16 phases x 64 K-rows.

#define NT 256
#define PITCHB 144              // bf16 tile row pitch (bytes)
#define QTILEB (32 * PITCHB)    // 4608
#define KTILEB (64 * PITCHB)    // 9216
#define STGKV  16384            // 64 rows * 256 B (f32) per tensor
#define MSKB   8192             // 32 rows * 256 B per phase

#define SM_QH   0
#define SM_QL   (SM_QH + QTILEB)
#define SM_KH   (SM_QL + QTILEB)       // 9216
#define SM_KL   (SM_KH + KTILEB)
#define SM_VH   (SM_KL + KTILEB)
#define SM_VL   (SM_VH + KTILEB)
#define SM_STG  (SM_VL + KTILEB)       // 46080: K f32, V f32 at +STGKV
#define SM_MSK  (SM_STG + 2 * STGKV)   // 78848: 2 bufs x 8192
#define SM_Z    (SM_MSK + 2 * MSKB)    // 95232
#define SM_INVZ (SM_Z + 128)
#define SM_CTX  (SM_INVZ + 128)        // 95488, 8192 B
#define SM_TOTAL (SM_CTX + 8192)       // 103680 B  (x2 CTAs = 207360)

__device__ __forceinline__ uint32_t smem_u32(const void* p) {
    uint32_t a;
    asm("{ .reg .u64 t; cvta.to.shared.u64 t, %1; cvt.u32.u64 %0, t; }" : "=r"(a) : "l"(p));
    return a;
}
__device__ __forceinline__ uint32_t b2u(__nv_bfloat162 h) { return *(uint32_t*)&h; }

__device__ __forceinline__ void ldsm_x4(uint32_t a, uint32_t r[4]) {
    asm volatile("ldmatrix.sync.aligned.m8n8.x4.shared.b16 {%0,%1,%2,%3}, [%4];"
                 : "=r"(r[0]), "=r"(r[1]), "=r"(r[2]), "=r"(r[3]) : "r"(a));
}
__device__ __forceinline__ void ldsm_x2t(uint32_t a, uint32_t r[2]) {
    asm volatile("ldmatrix.sync.aligned.m8n8.x2.trans.shared.b16 {%0,%1}, [%2];"
                 : "=r"(r[0]), "=r"(r[1]) : "r"(a));
}
__device__ __forceinline__ void mma_bf16(float c[4], const uint32_t a[4], const uint32_t b[2]) {
    asm volatile("mma.sync.aligned.m16n8k16.row.col.f32.bf16.bf16.f32 "
                 "{%0,%1,%2,%3}, {%4,%5,%6,%7}, {%8,%9}, {%0,%1,%2,%3};"
                 : "+f"(c[0]), "+f"(c[1]), "+f"(c[2]), "+f"(c[3])
                 : "r"(a[0]), "r"(a[1]), "r"(a[2]), "r"(a[3]), "r"(b[0]), "r"(b[1]));
}
#define CP16(dst, src) \
    asm volatile("cp.async.cg.shared.global [%0], [%1], 16;" \
                 :: "r"(dst), "l"(__cvta_generic_to_global(src)) : "memory")

__device__ __forceinline__ void split2(float a, float b, uint32_t& h, uint32_t& l) {
    __nv_bfloat162 hh = __floats2bfloat162_rn(a, b);
    __nv_bfloat162 ll = __floats2bfloat162_rn(a - __low2float(hh), b - __high2float(hh));
    h = b2u(hh); l = b2u(ll);
}

__global__ __launch_bounds__(NT, 2)
void sdpa_mma_kernel(const float* __restrict__ Qg, const float* __restrict__ Kg,
                     const float* __restrict__ Vg, const uint32_t* __restrict__ Mg,
                     float* __restrict__ ctx, float* __restrict__ attn)
{
    extern __shared__ char sm[];
    const uint32_t sb = smem_u32(sm);

    const int tid  = threadIdx.x;
    const int wid  = tid >> 5;
    const int lane = tid & 31;
    const int g    = lane >> 2;
    const int t    = lane & 3;
    const int mh   = wid & 1;        // m16 row group (0..1)
    const int kw   = wid >> 1;       // n/k quadrant (0..3)

    const int b  = blockIdx.y;
    const int q0 = blockIdx.x * 32;

    const float* Qb = Qg + ((size_t)b * 1024 + q0) * 64;
    const float* Kb = Kg + (size_t)b * 1024 * 64;
    const float* Vb = Vg + (size_t)b * 1024 * 64;
    const uint32_t* Mb = Mg + ((size_t)b * 1024 + q0) * 1024;
    float* attnb = attn + ((size_t)b * 1024 + q0) * 1024;
    float* ctxb  = ctx  + ((size_t)b * 1024 + q0) * 64;

    const int r0 = mh * 16 + g;      // 0..31
    const int r1 = r0 + 8;

    // ---- prologue: issue KV(0) + mask(0) ----
    {
        #pragma unroll
        for (int it = 0; it < 4; it++) {
            int u = tid + it * NT;                 // 1024 units (64 rows x 16)
            int row = u >> 4, sg = u & 15;
            uint32_t kd = sb + SM_STG + (uint32_t)(row * 256 + sg * 16);
            CP16(kd, Kb + (size_t)row * 64 + sg * 4);
            CP16(kd + STGKV, Vb + (size_t)row * 64 + sg * 4);
        }
        #pragma unroll
        for (int it = 0; it < 2; it++) {
            int u = tid + it * NT;                 // 512 units (32 rows x 16)
            int row = u >> 4, sg = u & 15;
            uint32_t md = sb + SM_MSK + (uint32_t)(row * 256 + sg * 16);
            CP16(md, Mb + (size_t)row * 1024 + sg * 4);
        }
        asm volatile("cp.async.commit_group;" ::: "memory");
    }

    // ---- Q (32x64) * 0.125, split hi/lo bf16 ----
    if (tid < 32) ((float*)(sm + SM_Z))[tid] = 0.0f;
    #pragma unroll
    for (int it = 0; it < 2; it++) {
        int u = tid + it * NT;                     // 512 units
        int r = u >> 4, dg = u & 15;
        float4 v = *(const float4*)(Qb + (size_t)r * 64 + dg * 4);
        v.x *= 0.125f; v.y *= 0.125f; v.z *= 0.125f; v.w *= 0.125f;
        uint32_t h01, l01, h23, l23;
        split2(v.x, v.y, h01, l01);
        split2(v.z, v.w, h23, l23);
        int off = r * PITCHB + dg * 8;
        *(uint2*)(sm + SM_QH + off) = make_uint2(h01, h23);
        *(uint2*)(sm + SM_QL + off) = make_uint2(l01, l23);
    }
    __syncthreads();

    // ---- hoist Q fragments ----
    uint32_t QAh[4][4], QAl[4][4];
    #pragma unroll
    for (int kk = 0; kk < 4; kk++) {
        uint32_t arow = (uint32_t)(mh * 16 + (lane & 15)) * PITCHB
                      + (uint32_t)(kk * 16 + 8 * ((lane >> 4) & 1)) * 2;
        ldsm_x4(sb + SM_QH + arow, QAh[kk]);
        ldsm_x4(sb + SM_QL + arow, QAl[kk]);
    }

    float ctxa[8][4];
    #pragma unroll
    for (int j = 0; j < 8; j++)
        #pragma unroll
        for (int i = 0; i < 4; i++) ctxa[j][i] = 0.0f;
    float zr0 = 0.0f, zr1 = 0.0f;

    const uint32_t kfrag_base = sb + SM_KH + (uint32_t)kw * 16 * PITCHB
        + (uint32_t)((lane & 7) + 8 * ((lane >> 4) & 1)) * PITCHB
        + (uint32_t)(8 * ((lane >> 3) & 1)) * 2;
    const uint32_t vfrag_base = sb + SM_VH
        + (uint32_t)(kw * 16 + (lane & 7) + 8 * ((lane >> 3) & 1)) * PITCHB;

    for (int ph = 0; ph < 16; ph++) {
        asm volatile("cp.async.wait_group 0;" ::: "memory");
        __syncthreads();                           // staging+mask(ph) ready; tiles free

        // ---- shared convert: f32 staging -> bf16 hi/lo tiles ----
        {
            const float* Kf = (const float*)(sm + SM_STG);
            const float* Vf = (const float*)(sm + SM_STG + STGKV);
            #pragma unroll
            for (int it = 0; it < 4; it++) {
                int u = tid + it * NT;             // 1024 units
                int r = u >> 4, dg = u & 15;
                int off = r * PITCHB + dg * 8;
                float4 kv = *(const float4*)(Kf + r * 64 + dg * 4);
                uint32_t h01, l01, h23, l23;
                split2(kv.x, kv.y, h01, l01);
                split2(kv.z, kv.w, h23, l23);
                *(uint2*)(sm + SM_KH + off) = make_uint2(h01, h23);
                *(uint2*)(sm + SM_KL + off) = make_uint2(l01, l23);
                float4 vv = *(const float4*)(Vf + r * 64 + dg * 4);
                split2(vv.x, vv.y, h01, l01);
                split2(vv.z, vv.w, h23, l23);
                *(uint2*)(sm + SM_VH + off) = make_uint2(h01, h23);
                *(uint2*)(sm + SM_VL + off) = make_uint2(l01, l23);
            }
        }
        __syncthreads();                           // tiles ready; staging consumed

        // ---- early reissue: KV(ph+1) into (free) staging, mask(ph+1) ----
        if (ph < 15) {
            int nmb = (ph + 1) & 1;
            #pragma unroll
            for (int it = 0; it < 4; it++) {
                int u = tid + it * NT;             // 1024 units
                int row = u >> 4, sg = u & 15;
                uint32_t kd = sb + SM_STG + (uint32_t)(row * 256 + sg * 16);
                CP16(kd, Kb + (size_t)((ph + 1) * 64 + row) * 64 + sg * 4);
                CP16(kd + STGKV, Vb + (size_t)((ph + 1) * 64 + row) * 64 + sg * 4);
            }
            #pragma unroll
            for (int it = 0; it < 2; it++) {
                int u = tid + it * NT;
                int row = u >> 4, sg = u & 15;
                uint32_t md = sb + SM_MSK + (uint32_t)(nmb * MSKB + row * 256 + sg * 16);
                CP16(md, Mb + (size_t)row * 1024 + (ph + 1) * 64 + sg * 4);
            }
            asm volatile("cp.async.commit_group;" ::: "memory");
        }

        // ---- GEMM1: S(m16 x n16) = Q' @ Kc^T over k=64, 3 products ----
        float S[2][4];
        #pragma unroll
        for (int j = 0; j < 2; j++)
            #pragma unroll
            for (int i = 0; i < 4; i++) S[j][i] = 0.0f;

        #pragma unroll
        for (int kk = 0; kk < 4; kk++) {
            uint32_t ba = kfrag_base + (uint32_t)(kk * 16) * 2;
            uint32_t Bh[4], Bl[4];
            ldsm_x4(ba, Bh);
            ldsm_x4(ba + (SM_KL - SM_KH), Bl);
            mma_bf16(S[0], QAh[kk], Bh);
            mma_bf16(S[0], QAh[kk], Bl);
            mma_bf16(S[0], QAl[kk], Bh);
            uint32_t Bh1[2] = { Bh[2], Bh[3] };
            uint32_t Bl1[2] = { Bl[2], Bl[3] };
            mma_bf16(S[1], QAh[kk], Bh1);
            mma_bf16(S[1], QAh[kk], Bl1);
            mma_bf16(S[1], QAl[kk], Bh1);
        }

        // ---- epilogue: mask (smem), exp, unnorm attn, pack P hi/lo ----
        uint32_t Ph0[2], Ph1[2], Pl0[2], Pl1[2];
        {
            const uint32_t* Ms = (const uint32_t*)(sm + SM_MSK + (ph & 1) * MSKB);
            #pragma unroll
            for (int j = 0; j < 2; j++) {
                int cl = kw * 16 + j * 8 + 2 * t;          // col within 64-slice
                int col = ph * 64 + cl;
                uint2 m0 = *(const uint2*)(Ms + r0 * 64 + cl);
                uint2 m1 = *(const uint2*)(Ms + r1 * 64 + cl);
                float p00 = m0.x ? 0.0f : __expf(S[j][0]);
                float p01 = m0.y ? 0.0f : __expf(S[j][1]);
                float p10 = m1.x ? 0.0f : __expf(S[j][2]);
                float p11 = m1.y ? 0.0f : __expf(S[j][3]);
                zr0 += p00 + p01;
                zr1 += p10 + p11;
                *(float2*)(attnb + (size_t)r0 * 1024 + col) = make_float2(p00, p01);
                *(float2*)(attnb + (size_t)r1 * 1024 + col) = make_float2(p10, p11);
                split2(p00, p01, Ph0[j], Pl0[j]);
                split2(p10, p11, Ph1[j], Pl1[j]);
            }
        }

        // ---- GEMM2: ctx += P(m16 x k16) @ Vc(k16 x n64), 3 products ----
        {
            uint32_t Ahf[4] = { Ph0[0], Ph1[0], Ph0[1], Ph1[1] };
            uint32_t Alf[4] = { Pl0[0], Pl1[0], Pl0[1], Pl1[1] };
            #pragma unroll
            for (int j2 = 0; j2 < 8; j2++) {
                uint32_t va = vfrag_base + (uint32_t)(j2 * 16);
                uint32_t Bh[2], Bl[2];
                ldsm_x2t(va, Bh);
                ldsm_x2t(va + (SM_VL - SM_VH), Bl);
                mma_bf16(ctxa[j2], Ahf, Bh);
                mma_bf16(ctxa[j2], Ahf, Bl);
                mma_bf16(ctxa[j2], Alf, Bh);
            }
        }
        __syncthreads();   // tiles + mask buf consumed before next convert/reissue
    }

    // ---- Z: quad-reduce then smem atomic ----
    zr0 += __shfl_xor_sync(0xFFFFFFFFu, zr0, 1);
    zr0 += __shfl_xor_sync(0xFFFFFFFFu, zr0, 2);
    zr1 += __shfl_xor_sync(0xFFFFFFFFu, zr1, 1);
    zr1 += __shfl_xor_sync(0xFFFFFFFFu, zr1, 2);
    if (t == 0) {
        atomicAdd((float*)(sm + SM_Z) + r0, zr0);
        atomicAdd((float*)(sm + SM_Z) + r1, zr1);
    }
    __syncthreads();

    if (tid < 32)
        ((float*)(sm + SM_INVZ))[tid] = 1.0f / ((float*)(sm + SM_Z))[tid];
    float* sc = (float*)(sm + SM_CTX);
    #pragma unroll
    for (int it = 0; it < 8; it++) sc[tid + it * NT] = 0.0f;
    __syncthreads();

    // ---- ctx cross-warp reduce (kw quadrants) ----
    #pragma unroll
    for (int j = 0; j < 8; j++) {
        int cb = j * 8 + 2 * t;
        atomicAdd(&sc[r0 * 64 + cb],     ctxa[j][0]);
        atomicAdd(&sc[r0 * 64 + cb + 1], ctxa[j][1]);
        atomicAdd(&sc[r1 * 64 + cb],     ctxa[j][2]);
        atomicAdd(&sc[r1 * 64 + cb + 1], ctxa[j][3]);
    }
    __syncthreads();

    // ---- store ctx (scaled) ----
    const float* inv = (const float*)(sm + SM_INVZ);
    #pragma unroll
    for (int it = 0; it < 8; it++) {
        int u = tid + it * NT;           // 2048 units
        int r = u >> 6;
        ctxb[(size_t)r * 64 + (u & 63)] = sc[u] * inv[r];
    }

    // ---- rescale attn tile (L2-hot) ----
    #pragma unroll 4
    for (int it = 0; it < 32; it++) {
        int u = tid + it * NT;           // 8192 float4
        int r = u >> 8;
        float iz = inv[r];
        float4* p = (float4*)(attnb + (size_t)r * 1024) + (u & 255);
        float4 v = *p;
        v.x *= iz; v.y *= iz; v.z *= iz; v.w *= iz;
        *p = v;
    }
}

extern "C" void kernel_launch(void* const* d_in, const int* in_sizes, int n_in,
                              void* d_out, int out_size) {
    const float* q = (const float*)d_in[0];
    const float* k = (const float*)d_in[1];
    const float* v = (const float*)d_in[2];
    const uint32_t* m = (const uint32_t*)d_in[3];

    float* ctx  = (float*)d_out;
    float* attn = (float*)d_out + 32 * 1024 * 64;

    cudaFuncSetAttribute(sdpa_mma_kernel, cudaFuncAttributeMaxDynamicSharedMemorySize,
                         SM_TOTAL);

    dim3 grid(32, 32);   // (q tiles of 32, batch)
    sdpa_mma_kernel<<<grid, NT, SM_TOTAL>>>(q, k, v, m, ctx, attn);
}

// round 15
// speedup vs baseline: 2.7811x; 1.0353x over previous
#include <cuda_runtime.h>
#include <cuda_bf16.h>
#include <cstdint>

// SDPA via mma.sync bf16 hi/lo (3 products ~ fp32 accuracy).
// Prepass kernel converts Q/K/V fp32 -> bf16 hi/lo pitched tile images in
// __device__ scratch; main kernel cp.asyncs ready tiles (double-buffered,
// 1 barrier/phase) and runs GEMM1 -> masked exp -> GEMM2.
// B=32, Q=K=1024, D=64 fp32. out = [context | attn]. mask 4B, nonzero => p=0.
// Main CTA: 32 q rows, 8 warps = (mh 0..1) x (kw 0..3), 16 phases x 64 K-rows.

#define NT 256
#define PITCHB 144               // tile row pitch (bytes)
#define QTILEB (32 * PITCHB)     // 4608
#define KTILEB (64 * PITCHB)     // 9216
#define T4B    (4 * KTILEB)      // 36864: KH,KL,VH,VL per phase
#define MSKB   8192              // 32 rows * 256 B

// ---- main-kernel smem ----
#define SM_Q    0                         // QH + QL = 9216
#define SM_T    9216                      // 2 bufs x T4B = 73728
#define SM_MSK  (SM_T + 2 * T4B)          // 82944: 2 x 8192
#define SM_Z    (SM_MSK + 2 * MSKB)       // 99328
#define SM_INVZ (SM_Z + 128)
#define SM_CTX  (SM_INVZ + 128)           // 99584, 8192 B
#define SM_TOTAL (SM_CTX + 8192)          // 107776 B (x2 CTAs = 215552)

// ---- device scratch: converted tiles ----
// g_kv[b][ph] = {KH, KL, VH, VL} contiguous 36864 B
__device__ __align__(16) unsigned char g_kv[32][16][4][KTILEB];
// g_q[b][qt] = {QH, QL} contiguous 9216 B
__device__ __align__(16) unsigned char g_q[32][32][2][QTILEB];

__device__ __forceinline__ uint32_t smem_u32(const void* p) {
    uint32_t a;
    asm("{ .reg .u64 t; cvta.to.shared.u64 t, %1; cvt.u32.u64 %0, t; }" : "=r"(a) : "l"(p));
    return a;
}
__device__ __forceinline__ uint32_t b2u(__nv_bfloat162 h) { return *(uint32_t*)&h; }

__device__ __forceinline__ void ldsm_x4(uint32_t a, uint32_t r[4]) {
    asm volatile("ldmatrix.sync.aligned.m8n8.x4.shared.b16 {%0,%1,%2,%3}, [%4];"
                 : "=r"(r[0]), "=r"(r[1]), "=r"(r[2]), "=r"(r[3]) : "r"(a));
}
__device__ __forceinline__ void ldsm_x2t(uint32_t a, uint32_t r[2]) {
    asm volatile("ldmatrix.sync.aligned.m8n8.x2.trans.shared.b16 {%0,%1}, [%2];"
                 : "=r"(r[0]), "=r"(r[1]) : "r"(a));
}
__device__ __forceinline__ void mma_bf16(float c[4], const uint32_t a[4], const uint32_t b[2]) {
    asm volatile("mma.sync.aligned.m16n8k16.row.col.f32.bf16.bf16.f32 "
                 "{%0,%1,%2,%3}, {%4,%5,%6,%7}, {%8,%9}, {%0,%1,%2,%3};"
                 : "+f"(c[0]), "+f"(c[1]), "+f"(c[2]), "+f"(c[3])
                 : "r"(a[0]), "r"(a[1]), "r"(a[2]), "r"(a[3]), "r"(b[0]), "r"(b[1]));
}
#define CP16(dst, src) \
    asm volatile("cp.async.cg.shared.global [%0], [%1], 16;" \
                 :: "r"(dst), "l"(__cvta_generic_to_global(src)) : "memory")

__device__ __forceinline__ void split2(float a, float b, uint32_t& h, uint32_t& l) {
    __nv_bfloat162 hh = __floats2bfloat162_rn(a, b);
    __nv_bfloat162 ll = __floats2bfloat162_rn(a - __low2float(hh), b - __high2float(hh));
    h = b2u(hh); l = b2u(ll);
}

// ===================== prepass: fp32 -> bf16 hi/lo tile images =====================
__global__ __launch_bounds__(NT)
void prepass_kernel(const float* __restrict__ Qg, const float* __restrict__ Kg,
                    const float* __restrict__ Vg)
{
    const int bx = blockIdx.x;     // 0..15 KV phase, 16..47 Q tile
    const int b  = blockIdx.y;
    const int tid = threadIdx.x;

    if (bx < 16) {
        const float* Kb = Kg + ((size_t)b * 1024 + bx * 64) * 64;
        const float* Vb = Vg + ((size_t)b * 1024 + bx * 64) * 64;
        unsigned char* kh = g_kv[b][bx][0];
        unsigned char* kl = g_kv[b][bx][1];
        unsigned char* vh = g_kv[b][bx][2];
        unsigned char* vl = g_kv[b][bx][3];
        #pragma unroll
        for (int it = 0; it < 4; it++) {
            int u = tid + it * NT;          // 1024 units
            int row = u >> 4, dg = u & 15;
            int off = row * PITCHB + dg * 8;
            float4 kv = *(const float4*)(Kb + (size_t)row * 64 + dg * 4);
            uint32_t h01, l01, h23, l23;
            split2(kv.x, kv.y, h01, l01);
            split2(kv.z, kv.w, h23, l23);
            *(uint2*)(kh + off) = make_uint2(h01, h23);
            *(uint2*)(kl + off) = make_uint2(l01, l23);
            float4 vv = *(const float4*)(Vb + (size_t)row * 64 + dg * 4);
            split2(vv.x, vv.y, h01, l01);
            split2(vv.z, vv.w, h23, l23);
            *(uint2*)(vh + off) = make_uint2(h01, h23);
            *(uint2*)(vl + off) = make_uint2(l01, l23);
        }
    } else {
        const int qt = bx - 16;
        const float* Qb = Qg + ((size_t)b * 1024 + qt * 32) * 64;
        unsigned char* qh = g_q[b][qt][0];
        unsigned char* ql = g_q[b][qt][1];
        #pragma unroll
        for (int it = 0; it < 2; it++) {
            int u = tid + it * NT;          // 512 units
            int r = u >> 4, dg = u & 15;
            float4 v = *(const float4*)(Qb + (size_t)r * 64 + dg * 4);
            v.x *= 0.125f; v.y *= 0.125f; v.z *= 0.125f; v.w *= 0.125f;
            uint32_t h01, l01, h23, l23;
            split2(v.x, v.y, h01, l01);
            split2(v.z, v.w, h23, l23);
            int off = r * PITCHB + dg * 8;
            *(uint2*)(qh + off) = make_uint2(h01, h23);
            *(uint2*)(ql + off) = make_uint2(l01, l23);
        }
    }
}

// ===================== main kernel =====================
__global__ __launch_bounds__(NT, 2)
void sdpa_mma_kernel(const uint32_t* __restrict__ Mg,
                     float* __restrict__ ctx, float* __restrict__ attn)
{
    extern __shared__ char sm[];
    const uint32_t sb = smem_u32(sm);

    const int tid  = threadIdx.x;
    const int wid  = tid >> 5;
    const int lane = tid & 31;
    const int g    = lane >> 2;
    const int t    = lane & 3;
    const int mh   = wid & 1;
    const int kw   = wid >> 1;

    const int b  = blockIdx.y;
    const int qt = blockIdx.x;
    const int q0 = qt * 32;

    const uint32_t* Mb = Mg + ((size_t)b * 1024 + q0) * 1024;
    float* attnb = attn + ((size_t)b * 1024 + q0) * 1024;
    float* ctxb  = ctx  + ((size_t)b * 1024 + q0) * 64;

    const int r0 = mh * 16 + g;
    const int r1 = r0 + 8;

    if (tid < 32) ((float*)(sm + SM_Z))[tid] = 0.0f;

    // ---- prologue: G0 = Q tiles + KV tiles(0) + mask(0) ----
    {
        const unsigned char* gq = g_q[b][qt][0];
        for (int u = tid; u < 576; u += NT)                 // 9216 B
            CP16(sb + SM_Q + u * 16, gq + u * 16);
        const unsigned char* gt = g_kv[b][0][0];
        for (int u = tid; u < 2304; u += NT)                // 36864 B
            CP16(sb + SM_T + u * 16, gt + u * 16);
        #pragma unroll
        for (int it = 0; it < 2; it++) {
            int u = tid + it * NT;                          // 512 units
            int row = u >> 4, sg = u & 15;
            CP16(sb + SM_MSK + (uint32_t)(row * 256 + sg * 16),
                 Mb + (size_t)row * 1024 + sg * 4);
        }
        asm volatile("cp.async.commit_group;" ::: "memory");
        asm volatile("cp.async.wait_group 0;" ::: "memory");
    }
    __syncthreads();

    // ---- hoist Q fragments ----
    uint32_t QAh[4][4], QAl[4][4];
    #pragma unroll
    for (int kk = 0; kk < 4; kk++) {
        uint32_t arow = (uint32_t)(mh * 16 + (lane & 15)) * PITCHB
                      + (uint32_t)(kk * 16 + 8 * ((lane >> 4) & 1)) * 2;
        ldsm_x4(sb + SM_Q + arow, QAh[kk]);
        ldsm_x4(sb + SM_Q + QTILEB + arow, QAl[kk]);
    }

    float ctxa[8][4];
    #pragma unroll
    for (int j = 0; j < 8; j++)
        #pragma unroll
        for (int i = 0; i < 4; i++) ctxa[j][i] = 0.0f;
    float zr0 = 0.0f, zr1 = 0.0f;

    const uint32_t kfrag_off = (uint32_t)kw * 16 * PITCHB
        + (uint32_t)((lane & 7) + 8 * ((lane >> 4) & 1)) * PITCHB
        + (uint32_t)(8 * ((lane >> 3) & 1)) * 2;
    const uint32_t vfrag_off = 2 * KTILEB
        + (uint32_t)(kw * 16 + (lane & 7) + 8 * ((lane >> 3) & 1)) * PITCHB;

    for (int ph = 0; ph < 16; ph++) {
        const int buf = ph & 1;

        // issue next phase into other buffer (consumers of it finished last phase)
        if (ph < 15) {
            const unsigned char* gt = g_kv[b][ph + 1][0];
            uint32_t td = sb + SM_T + (uint32_t)((buf ^ 1) * T4B);
            for (int u = tid; u < 2304; u += NT)
                CP16(td + u * 16, gt + u * 16);
            uint32_t md = sb + SM_MSK + (uint32_t)((buf ^ 1) * MSKB);
            #pragma unroll
            for (int it = 0; it < 2; it++) {
                int u = tid + it * NT;
                int row = u >> 4, sg = u & 15;
                CP16(md + (uint32_t)(row * 256 + sg * 16),
                     Mb + (size_t)row * 1024 + (ph + 1) * 64 + sg * 4);
            }
            asm volatile("cp.async.commit_group;" ::: "memory");
        }

        const uint32_t tb = sb + SM_T + (uint32_t)(buf * T4B);

        // ---- GEMM1: S(m16 x n16) = Q' @ Kc^T over k=64, 3 products ----
        float S[2][4];
        #pragma unroll
        for (int j = 0; j < 2; j++)
            #pragma unroll
            for (int i = 0; i < 4; i++) S[j][i] = 0.0f;

        #pragma unroll
        for (int kk = 0; kk < 4; kk++) {
            uint32_t ba = tb + kfrag_off + (uint32_t)(kk * 16) * 2;
            uint32_t Bh[4], Bl[4];
            ldsm_x4(ba, Bh);
            ldsm_x4(ba + KTILEB, Bl);
            mma_bf16(S[0], QAh[kk], Bh);
            mma_bf16(S[0], QAh[kk], Bl);
            mma_bf16(S[0], QAl[kk], Bh);
            uint32_t Bh1[2] = { Bh[2], Bh[3] };
            uint32_t Bl1[2] = { Bl[2], Bl[3] };
            mma_bf16(S[1], QAh[kk], Bh1);
            mma_bf16(S[1], QAh[kk], Bl1);
            mma_bf16(S[1], QAl[kk], Bh1);
        }

        // ---- epilogue: mask (smem), exp, unnorm attn, pack P hi/lo ----
        uint32_t Ph0[2], Ph1[2], Pl0[2], Pl1[2];
        {
            const uint32_t* Ms = (const uint32_t*)(sm + SM_MSK + buf * MSKB);
            #pragma unroll
            for (int j = 0; j < 2; j++) {
                int cl = kw * 16 + j * 8 + 2 * t;
                int col = ph * 64 + cl;
                uint2 m0 = *(const uint2*)(Ms + r0 * 64 + cl);
                uint2 m1 = *(const uint2*)(Ms + r1 * 64 + cl);
                float p00 = m0.x ? 0.0f : __expf(S[j][0]);
                float p01 = m0.y ? 0.0f : __expf(S[j][1]);
                float p10 = m1.x ? 0.0f : __expf(S[j][2]);
                float p11 = m1.y ? 0.0f : __expf(S[j][3]);
                zr0 += p00 + p01;
                zr1 += p10 + p11;
                *(float2*)(attnb + (size_t)r0 * 1024 + col) = make_float2(p00, p01);
                *(float2*)(attnb + (size_t)r1 * 1024 + col) = make_float2(p10, p11);
                split2(p00, p01, Ph0[j], Pl0[j]);
                split2(p10, p11, Ph1[j], Pl1[j]);
            }
        }

        // ---- GEMM2: ctx += P(m16 x k16) @ Vc(k16 x n64), 3 products ----
        {
            uint32_t Ahf[4] = { Ph0[0], Ph1[0], Ph0[1], Ph1[1] };
            uint32_t Alf[4] = { Pl0[0], Pl1[0], Pl0[1], Pl1[1] };
            #pragma unroll
            for (int j2 = 0; j2 < 8; j2++) {
                uint32_t va = tb + vfrag_off + (uint32_t)(j2 * 16);
                uint32_t Bh[2], Bl[2];
                ldsm_x2t(va, Bh);
                ldsm_x2t(va + KTILEB, Bl);
                mma_bf16(ctxa[j2], Ahf, Bh);
                mma_bf16(ctxa[j2], Ahf, Bl);
                mma_bf16(ctxa[j2], Alf, Bh);
            }
        }

        if (ph < 15) {
            asm volatile("cp.async.wait_group 0;" ::: "memory");
            __syncthreads();    // next buffers ready; this phase's consumers done
        }
    }

    // ---- Z: quad-reduce then smem atomic ----
    zr0 += __shfl_xor_sync(0xFFFFFFFFu, zr0, 1);
    zr0 += __shfl_xor_sync(0xFFFFFFFFu, zr0, 2);
    zr1 += __shfl_xor_sync(0xFFFFFFFFu, zr1, 1);
    zr1 += __shfl_xor_sync(0xFFFFFFFFu, zr1, 2);
    if (t == 0) {
        atomicAdd((float*)(sm + SM_Z) + r0, zr0);
        atomicAdd((float*)(sm + SM_Z) + r1, zr1);
    }
    __syncthreads();

    if (tid < 32)
        ((float*)(sm + SM_INVZ))[tid] = 1.0f / ((float*)(sm + SM_Z))[tid];
    float* sc = (float*)(sm + SM_CTX);
    #pragma unroll
    for (int it = 0; it < 8; it++) sc[tid + it * NT] = 0.0f;
    __syncthreads();

    // ---- ctx cross-warp reduce (kw quadrants) ----
    #pragma unroll
    for (int j = 0; j < 8; j++) {
        int cb = j * 8 + 2 * t;
        atomicAdd(&sc[r0 * 64 + cb],     ctxa[j][0]);
        atomicAdd(&sc[r0 * 64 + cb + 1], ctxa[j][1]);
        atomicAdd(&sc[r1 * 64 + cb],     ctxa[j][2]);
        atomicAdd(&sc[r1 * 64 + cb + 1], ctxa[j][3]);
    }
    __syncthreads();

    // ---- store ctx (scaled) ----
    const float* inv = (const float*)(sm + SM_INVZ);
    #pragma unroll
    for (int it = 0; it < 8; it++) {
        int u = tid + it * NT;
        int r = u >> 6;
        ctxb[(size_t)r * 64 + (u & 63)] = sc[u] * inv[r];
    }

    // ---- rescale attn tile (L2-hot) ----
    #pragma unroll 4
    for (int it = 0; it < 32; it++) {
        int u = tid + it * NT;
        int r = u >> 8;
        float iz = inv[r];
        float4* p = (float4*)(attnb + (size_t)r * 1024) + (u & 255);
        float4 v = *p;
        v.x *= iz; v.y *= iz; v.z *= iz; v.w *= iz;
        *p = v;
    }
}

extern "C" void kernel_launch(void* const* d_in, const int* in_sizes, int n_in,
                              void* d_out, int out_size) {
    const float* q = (const float*)d_in[0];
    const float* k = (const float*)d_in[1];
    const float* v = (const float*)d_in[2];
    const uint32_t* m = (const uint32_t*)d_in[3];

    float* ctx  = (float*)d_out;
    float* attn = (float*)d_out + 32 * 1024 * 64;

    cudaFuncSetAttribute(sdpa_mma_kernel, cudaFuncAttributeMaxDynamicSharedMemorySize,
                         SM_TOTAL);

    prepass_kernel<<<dim3(48, 32), NT>>>(q, k, v);
    sdpa_mma_kernel<<<dim3(32, 32), NT, SM_TOTAL>>>(m, ctx, attn);
}